// round 4
// baseline (speedup 1.0000x reference)
#include <cuda_runtime.h>

#define B_VOX   256
#define NPC     40
#define NE      32
#define ORD     2                    // EPG orders per lane
#define LPC     16                   // lanes per compartment (ORD*LPC = 32 orders)
#define CPW     2                    // compartments per warp
#define WARPS   (NPC / CPW)          // 20
#define THREADS (WARPS * 32)         // 640

// EPG step x' = S·(D·T·D)·S·x (D commutes with S). Order o = 2*s + j + 1,
// sub-lane s = lane&15 (0..15), j = 0..1; compartment = wz*2 + (lane>>4).
// Fused 3x3 per compartment:  mF =  A·sF + B·sG + C·Z
//                             mG =  B·sF + A·sG - C·Z
//                             mZ =  Dz·(sG - sF) + Ez·Z
// shift1: sF[o]=F[o-1] (sF[1]=x0),  sG[o]=G[o+1] (sG[32]=0),  mx0=e2²·G[1]
// shift2: F[o]=mF[o-1] (F[1]=mx0),  G[o]=mG[o+1] (G[32]=0),   echo=mG[1]

__global__ __launch_bounds__(THREADS) void epg_kernel(
    const float* __restrict__ refoc,    // (256,)
    const float* __restrict__ t2s,      // (256, 40)
    const float* __restrict__ wts,      // (256, 40)
    float* __restrict__ out)            // (256, 32)
{
    const int b    = blockIdx.x;
    const int lane = threadIdx.x & 31;
    const int wz   = threadIdx.x >> 5;
    const int s    = lane & (LPC - 1);       // sub-lane within compartment
    const int grp  = lane >> 4;              // compartment group within warp
    const bool sLo = (s == 0);
    const bool sHi = (s == LPC - 1);
    const unsigned FULL = 0xFFFFFFFFu;

    __shared__ float smem[NPC][NE + 1];      // +1 pad: conflict-free leader STS

    // per-voxel rotation constants
    const float a  = refoc[b] * 0.017453292519943295f;
    const float ah = 0.5f * a;
    const float sa = sinf(a),  ca = cosf(a);
    const float sh = sinf(ah), ch = cosf(ah);
    const float c2 = ch * ch,  s2 = sh * sh;
    const float e1   = 0.99501247919268231f;     // exp(-5/1000)
    const float e1sq = e1 * e1;

    // per-compartment fused coefficients
    const int   c    = wz * CPW + grp;
    const float e2   = expf(-5.0f / t2s[b * NPC + c]);
    const float e2sq = e2 * e2;
    const float A    = c2 * e2sq;
    const float Bc   = s2 * e2sq;
    const float Cc   = sa * e2 * e1;
    const float Dz   = 0.5f * sa * e1 * e2;
    const float Ez   = ca * e1sq;
    const float w    = wts[b * NPC + c];

    // initial state: x0 = sin(ah); G(order 1) = cos(ah)
    float F0 = 0.f, F1 = 0.f;
    float G0 = sLo ? ch : 0.f, G1 = 0.f;
    float Z0 = 0.f, Z1 = 0.f;
    float x0 = sh;                           // meaningful on sub-lane 0

    #pragma unroll 4
    for (int k = 0; k < NE; ++k) {
        // ---- shift 1: only boundary elements cross lanes (width-16 groups) ----
        const float fc = __shfl_up_sync  (FULL, F1, 1, LPC);
        const float gc = __shfl_down_sync(FULL, G0, 1, LPC);
        const float mx0 = e2sq * G0;         // sub-lane 0: order-1 G pre-shift

        const float sF0 = sLo ? x0 : fc;
        const float sF1 = F0;
        const float sG0 = G1;
        const float sG1 = sHi ? 0.f : gc;

        // ---- fused rotation+decay ----
        const float t0 = Cc * Z0;
        const float t1 = Cc * Z1;
        const float mF0 = fmaf(A,  sF0, fmaf(Bc, sG0,  t0));
        const float mG0 = fmaf(Bc, sF0, fmaf(A,  sG0, -t0));
        const float mZ0 = fmaf(Ez, Z0, Dz * (sG0 - sF0));
        const float mF1 = fmaf(A,  sF1, fmaf(Bc, sG1,  t1));
        const float mG1 = fmaf(Bc, sF1, fmaf(A,  sG1, -t1));
        const float mZ1 = fmaf(Ez, Z1, Dz * (sG1 - sF1));

        // ---- shift 2 ----
        const float fc2 = __shfl_up_sync  (FULL, mF1, 1, LPC);
        const float gc2 = __shfl_down_sync(FULL, mG0, 1, LPC);
        F0 = sLo ? mx0 : fc2;
        F1 = mF0;
        G0 = mG1;
        G1 = sHi ? 0.f : gc2;
        Z0 = mZ0;
        Z1 = mZ1;
        x0 = mG0;                            // new x0 (= echo on sub-lane 0)

        if (sLo) smem[c][k] = w * mG0;       // weighted echo, 1 predicated STS
    }

    __syncthreads();

    // warp 0: sum 40 compartments per echo, normalize by echo 0
    if (threadIdx.x < 32) {
        float acc = 0.0f;
        #pragma unroll
        for (int r = 0; r < NPC; ++r) acc += smem[r][lane];
        const float acc0 = __shfl_sync(FULL, acc, 0);
        out[b * NE + lane] = acc / acc0;
    }
}

extern "C" void kernel_launch(void* const* d_in, const int* in_sizes, int n_in,
                              void* d_out, int out_size) {
    const float* refoc = (const float*)d_in[0];
    const float* t2s   = (const float*)d_in[1];
    const float* wts   = (const float*)d_in[2];
    float* out = (float*)d_out;
    epg_kernel<<<B_VOX, THREADS>>>(refoc, t2s, wts, out);
}